// round 9
// baseline (speedup 1.0000x reference)
#include <cuda_runtime.h>
#include <cuda_bf16.h>
#include <math.h>

// ---------------------------------------------------------------------------
// FPGNN forward. R9:
//  - big GEMMs (Wh, Wx): 1x tf32 mma.sync
//  - tail GEMMs (fc1, fc2, q, v, o, ffn1): 3x tf32 (split hi/lo, ~fp32 acc)
//  - attn1/attn2 AV products: tf32 mma.sync on smem tiles
// ---------------------------------------------------------------------------

#define Bq 512
#define Nn 128
#define F_IN 133
#define NHEADS 8
#define NHID 64
#define HID 512
#define FP_DIM 1489
#define TASKS 12

typedef unsigned long long u64;
typedef unsigned int u32;

__device__ __forceinline__ u32 to_tf32(float f) {
    u32 r; asm("cvt.rna.tf32.f32 %0, %1;" : "=r"(r) : "f"(f)); return r;
}
__device__ __forceinline__ void mma_tf32(float* d, const u32* a, const u32* b) {
    asm volatile(
        "mma.sync.aligned.m16n8k8.row.col.f32.tf32.tf32.f32 "
        "{%0,%1,%2,%3}, {%4,%5,%6,%7}, {%8,%9}, {%0,%1,%2,%3};\n"
        : "+f"(d[0]), "+f"(d[1]), "+f"(d[2]), "+f"(d[3])
        : "r"(a[0]), "r"(a[1]), "r"(a[2]), "r"(a[3]), "r"(b[0]), "r"(b[1]));
}
__device__ __forceinline__ float elu1(float v) {
    return v > 0.f ? v : (__expf(v) - 1.f);
}

// ---- scratch (device globals; no allocation allowed) ----
__device__ float g_Wcat[F_IN * HID];
__device__ float g_Wh[(size_t)Bq * Nn * HID];
__device__ float g_s1[Bq * NHEADS * Nn];
__device__ float g_s2[Bq * NHEADS * Nn];
__device__ float g_x[(size_t)Bq * Nn * HID];
__device__ float g_Wx[(size_t)Bq * Nn * HID];
__device__ float g_t1[Bq * Nn];
__device__ float g_t2[Bq * Nn];
__device__ float g_gatp[Bq * 2 * HID];
__device__ float g_gat[Bq * HID];
__device__ float g_fpnh[Bq * HID];
__device__ float g_fpn[Bq * HID];
__device__ float g_buf1[Bq * HID];
__device__ float g_buf2[Bq * HID];

// ---------------------------------------------------------------------------
// 1x tf32 GEMM (fast path, big GEMMs). Same as R8 (validated).
// flags: 1 = bias, 2 = relu, 4 = accumulate
// ---------------------------------------------------------------------------
#define SA_STRIDE 20
#define SB_STRIDE 136

__global__ __launch_bounds__(256) void sgemm_tc_kernel(
    const float* __restrict__ A, const float* __restrict__ B,
    const float* __restrict__ bias, float* __restrict__ C,
    int M, int N, int K, int flags)
{
    __shared__ u32 sA[2][128 * SA_STRIDE];
    __shared__ u32 sB[2][16 * SB_STRIDE];

    int tid = threadIdx.x;
    int warp = tid >> 5, lane = tid & 31;
    int wr = warp >> 2, wc = warp & 3;
    int bm = blockIdx.y * 128;
    int bn = blockIdx.x * 128;
    int lr4 = lane >> 2, lc4 = lane & 3;

    float acc[4][4][4];
#pragma unroll
    for (int mt = 0; mt < 4; mt++)
#pragma unroll
        for (int nt = 0; nt < 4; nt++)
#pragma unroll
            for (int i = 0; i < 4; i++) acc[mt][nt][i] = 0.f;

    const int Ktiles = (K + 15) / 16;
    int aRow0 = tid >> 2,         aK0 = (tid & 3) * 4;
    int aRow1 = (tid + 256) >> 2, aK1 = ((tid + 256) & 3) * 4;
    int bK0 = tid >> 5,           bN0 = (tid & 31) * 4;
    int bK1 = (tid + 256) >> 5,   bN1 = ((tid + 256) & 31) * 4;

    float ar[2][4], br[2][4];
    {
#pragma unroll
        for (int i = 0; i < 4; i++) {
            int k = aK0 + i;
            ar[0][i] = (k < K) ? A[(size_t)(bm + aRow0) * K + k] : 0.f;
            k = aK1 + i;
            ar[1][i] = (k < K) ? A[(size_t)(bm + aRow1) * K + k] : 0.f;
        }
        if (bK0 < K) *(float4*)br[0] = *(const float4*)(B + (size_t)bK0 * N + bn + bN0);
        else { br[0][0] = br[0][1] = br[0][2] = br[0][3] = 0.f; }
        if (bK1 < K) *(float4*)br[1] = *(const float4*)(B + (size_t)bK1 * N + bn + bN1);
        else { br[1][0] = br[1][1] = br[1][2] = br[1][3] = 0.f; }
    }
#pragma unroll
    for (int i = 0; i < 4; i++) {
        sA[0][aRow0 * SA_STRIDE + aK0 + i] = to_tf32(ar[0][i]);
        sA[0][aRow1 * SA_STRIDE + aK1 + i] = to_tf32(ar[1][i]);
        sB[0][bK0 * SB_STRIDE + bN0 + i] = to_tf32(br[0][i]);
        sB[0][bK1 * SB_STRIDE + bN1 + i] = to_tf32(br[1][i]);
    }
    __syncthreads();

    int buf = 0;
    for (int t = 0; t < Ktiles; t++) {
        bool has_next = (t + 1 < Ktiles);
        if (has_next) {
            int k0 = (t + 1) * 16;
#pragma unroll
            for (int i = 0; i < 4; i++) {
                int k = k0 + aK0 + i;
                ar[0][i] = (k < K) ? A[(size_t)(bm + aRow0) * K + k] : 0.f;
                k = k0 + aK1 + i;
                ar[1][i] = (k < K) ? A[(size_t)(bm + aRow1) * K + k] : 0.f;
            }
            int k = k0 + bK0;
            if (k < K) *(float4*)br[0] = *(const float4*)(B + (size_t)k * N + bn + bN0);
            else { br[0][0] = br[0][1] = br[0][2] = br[0][3] = 0.f; }
            k = k0 + bK1;
            if (k < K) *(float4*)br[1] = *(const float4*)(B + (size_t)k * N + bn + bN1);
            else { br[1][0] = br[1][1] = br[1][2] = br[1][3] = 0.f; }
        }

        const u32* cA = sA[buf];
        const u32* cB = sB[buf];
#pragma unroll
        for (int kk = 0; kk < 16; kk += 8) {
            u32 afr[4][4], bfr[4][2];
#pragma unroll
            for (int mt = 0; mt < 4; mt++) {
                int r0 = wr * 64 + mt * 16 + lr4;
                int c0 = kk + lc4;
                afr[mt][0] = cA[r0 * SA_STRIDE + c0];
                afr[mt][1] = cA[(r0 + 8) * SA_STRIDE + c0];
                afr[mt][2] = cA[r0 * SA_STRIDE + c0 + 4];
                afr[mt][3] = cA[(r0 + 8) * SA_STRIDE + c0 + 4];
            }
#pragma unroll
            for (int nt = 0; nt < 4; nt++) {
                int col = wc * 32 + nt * 8 + lr4;
                bfr[nt][0] = cB[(kk + lc4) * SB_STRIDE + col];
                bfr[nt][1] = cB[(kk + lc4 + 4) * SB_STRIDE + col];
            }
#pragma unroll
            for (int mt = 0; mt < 4; mt++)
#pragma unroll
                for (int nt = 0; nt < 4; nt++)
                    mma_tf32(acc[mt][nt], afr[mt], bfr[nt]);
        }

        if (has_next) {
#pragma unroll
            for (int i = 0; i < 4; i++) {
                sA[buf ^ 1][aRow0 * SA_STRIDE + aK0 + i] = to_tf32(ar[0][i]);
                sA[buf ^ 1][aRow1 * SA_STRIDE + aK1 + i] = to_tf32(ar[1][i]);
                sB[buf ^ 1][bK0 * SB_STRIDE + bN0 + i] = to_tf32(br[0][i]);
                sB[buf ^ 1][bK1 * SB_STRIDE + bN1 + i] = to_tf32(br[1][i]);
            }
        }
        __syncthreads();
        buf ^= 1;
    }

#pragma unroll
    for (int mt = 0; mt < 4; mt++) {
#pragma unroll
        for (int nt = 0; nt < 4; nt++) {
            int col = bn + wc * 32 + nt * 8 + lc4 * 2;
#pragma unroll
            for (int half = 0; half < 2; half++) {
                int row = bm + wr * 64 + mt * 16 + lr4 + half * 8;
                float2 v = make_float2(acc[mt][nt][half * 2],
                                       acc[mt][nt][half * 2 + 1]);
                if (flags & 4) {
                    float2 c = *(const float2*)&C[(size_t)row * N + col];
                    v.x += c.x; v.y += c.y;
                }
                if (flags & 1) { v.x += bias[col]; v.y += bias[col + 1]; }
                if (flags & 2) { v.x = fmaxf(v.x, 0.f); v.y = fmaxf(v.y, 0.f); }
                *(float2*)&C[(size_t)row * N + col] = v;
            }
        }
    }
}

// ---------------------------------------------------------------------------
// 3x tf32 precise GEMM (tail GEMMs): a=a_hi+a_lo, b=b_hi+b_lo,
// d += ah*bh + al*bh + ah*bl  (~fp32 accuracy). Single-buffered.
// ---------------------------------------------------------------------------
__global__ __launch_bounds__(256) void sgemm_tc3_kernel(
    const float* __restrict__ A, const float* __restrict__ B,
    const float* __restrict__ bias, float* __restrict__ C,
    int M, int N, int K, int flags)
{
    __shared__ u32 sAhi[128 * SA_STRIDE], sAlo[128 * SA_STRIDE];
    __shared__ u32 sBhi[16 * SB_STRIDE],  sBlo[16 * SB_STRIDE];

    int tid = threadIdx.x;
    int warp = tid >> 5, lane = tid & 31;
    int wr = warp >> 2, wc = warp & 3;
    int bm = blockIdx.y * 128;
    int bn = blockIdx.x * 128;
    int lr4 = lane >> 2, lc4 = lane & 3;

    float acc[4][4][4];
#pragma unroll
    for (int mt = 0; mt < 4; mt++)
#pragma unroll
        for (int nt = 0; nt < 4; nt++)
#pragma unroll
            for (int i = 0; i < 4; i++) acc[mt][nt][i] = 0.f;

    const int Ktiles = (K + 15) / 16;
    int aRow0 = tid >> 2,         aK0 = (tid & 3) * 4;
    int aRow1 = (tid + 256) >> 2, aK1 = ((tid + 256) & 3) * 4;
    int bK0 = tid >> 5,           bN0 = (tid & 31) * 4;
    int bK1 = (tid + 256) >> 5,   bN1 = ((tid + 256) & 31) * 4;

    for (int t = 0; t < Ktiles; t++) {
        int k0 = t * 16;
#pragma unroll
        for (int i = 0; i < 4; i++) {
            int k = k0 + aK0 + i;
            float a0 = (k < K) ? A[(size_t)(bm + aRow0) * K + k] : 0.f;
            u32 hi = to_tf32(a0);
            sAhi[aRow0 * SA_STRIDE + aK0 + i] = hi;
            sAlo[aRow0 * SA_STRIDE + aK0 + i] = to_tf32(a0 - __uint_as_float(hi));
            k = k0 + aK1 + i;
            a0 = (k < K) ? A[(size_t)(bm + aRow1) * K + k] : 0.f;
            hi = to_tf32(a0);
            sAhi[aRow1 * SA_STRIDE + aK1 + i] = hi;
            sAlo[aRow1 * SA_STRIDE + aK1 + i] = to_tf32(a0 - __uint_as_float(hi));
        }
        {
            float b0[4], b1[4];
            int k = k0 + bK0;
            if (k < K) *(float4*)b0 = *(const float4*)(B + (size_t)k * N + bn + bN0);
            else { b0[0] = b0[1] = b0[2] = b0[3] = 0.f; }
            k = k0 + bK1;
            if (k < K) *(float4*)b1 = *(const float4*)(B + (size_t)k * N + bn + bN1);
            else { b1[0] = b1[1] = b1[2] = b1[3] = 0.f; }
#pragma unroll
            for (int i = 0; i < 4; i++) {
                u32 hi = to_tf32(b0[i]);
                sBhi[bK0 * SB_STRIDE + bN0 + i] = hi;
                sBlo[bK0 * SB_STRIDE + bN0 + i] = to_tf32(b0[i] - __uint_as_float(hi));
                hi = to_tf32(b1[i]);
                sBhi[bK1 * SB_STRIDE + bN1 + i] = hi;
                sBlo[bK1 * SB_STRIDE + bN1 + i] = to_tf32(b1[i] - __uint_as_float(hi));
            }
        }
        __syncthreads();

#pragma unroll
        for (int kk = 0; kk < 16; kk += 8) {
            u32 ah[4][4], al[4][4], bh[4][2], bl[4][2];
#pragma unroll
            for (int mt = 0; mt < 4; mt++) {
                int r0 = wr * 64 + mt * 16 + lr4;
                int c0 = kk + lc4;
                ah[mt][0] = sAhi[r0 * SA_STRIDE + c0];
                ah[mt][1] = sAhi[(r0 + 8) * SA_STRIDE + c0];
                ah[mt][2] = sAhi[r0 * SA_STRIDE + c0 + 4];
                ah[mt][3] = sAhi[(r0 + 8) * SA_STRIDE + c0 + 4];
                al[mt][0] = sAlo[r0 * SA_STRIDE + c0];
                al[mt][1] = sAlo[(r0 + 8) * SA_STRIDE + c0];
                al[mt][2] = sAlo[r0 * SA_STRIDE + c0 + 4];
                al[mt][3] = sAlo[(r0 + 8) * SA_STRIDE + c0 + 4];
            }
#pragma unroll
            for (int nt = 0; nt < 4; nt++) {
                int col = wc * 32 + nt * 8 + lr4;
                bh[nt][0] = sBhi[(kk + lc4) * SB_STRIDE + col];
                bh[nt][1] = sBhi[(kk + lc4 + 4) * SB_STRIDE + col];
                bl[nt][0] = sBlo[(kk + lc4) * SB_STRIDE + col];
                bl[nt][1] = sBlo[(kk + lc4 + 4) * SB_STRIDE + col];
            }
#pragma unroll
            for (int mt = 0; mt < 4; mt++)
#pragma unroll
                for (int nt = 0; nt < 4; nt++) {
                    mma_tf32(acc[mt][nt], ah[mt], bh[nt]);
                    mma_tf32(acc[mt][nt], al[mt], bh[nt]);
                    mma_tf32(acc[mt][nt], ah[mt], bl[nt]);
                }
        }
        __syncthreads();
    }

#pragma unroll
    for (int mt = 0; mt < 4; mt++) {
#pragma unroll
        for (int nt = 0; nt < 4; nt++) {
            int col = bn + wc * 32 + nt * 8 + lc4 * 2;
#pragma unroll
            for (int half = 0; half < 2; half++) {
                int row = bm + wr * 64 + mt * 16 + lr4 + half * 8;
                float2 v = make_float2(acc[mt][nt][half * 2],
                                       acc[mt][nt][half * 2 + 1]);
                if (flags & 4) {
                    float2 c = *(const float2*)&C[(size_t)row * N + col];
                    v.x += c.x; v.y += c.y;
                }
                if (flags & 1) { v.x += bias[col]; v.y += bias[col + 1]; }
                if (flags & 2) { v.x = fmaxf(v.x, 0.f); v.y = fmaxf(v.y, 0.f); }
                *(float2*)&C[(size_t)row * N + col] = v;
            }
        }
    }
}

// ---------------------------------------------------------------------------
// W_heads [8,133,64] -> Wcat [133, 512]
// ---------------------------------------------------------------------------
__global__ void wcat_kernel(const float* __restrict__ W_heads)
{
    int idx = blockIdx.x * blockDim.x + threadIdx.x;
    if (idx >= NHEADS * F_IN * NHID) return;
    int h = idx / (F_IN * NHID);
    int rem = idx - h * (F_IN * NHID);
    int f = rem / NHID;
    int d = rem - f * NHID;
    g_Wcat[f * HID + h * NHID + d] = W_heads[idx];
}

// ---------------------------------------------------------------------------
// s1/s2 head scores (warp per row, 64-length dot)
// ---------------------------------------------------------------------------
__global__ __launch_bounds__(256) void s12_kernel(
    const float* __restrict__ a1, const float* __restrict__ a2)
{
    int gw = (blockIdx.x * blockDim.x + threadIdx.x) >> 5;
    int lane = threadIdx.x & 31;
    if (gw >= Bq * NHEADS * Nn) return;
    int n  = gw & 127;
    int hh = (gw >> 7) & 7;
    int b  = gw >> 10;
    const float* row = g_Wh + ((size_t)b * Nn + n) * HID + hh * NHID;
    const float* av1 = a1 + hh * NHID;
    const float* av2 = a2 + hh * NHID;
    float x0 = row[lane], x1 = row[lane + 32];
    float r1 = x0 * av1[lane] + x1 * av1[lane + 32];
    float r2 = x0 * av2[lane] + x1 * av2[lane + 32];
#pragma unroll
    for (int o = 16; o; o >>= 1) {
        r1 += __shfl_xor_sync(0xffffffffu, r1, o);
        r2 += __shfl_xor_sync(0xffffffffu, r2, o);
    }
    if (lane == 0) {
        int o = (b * NHEADS + hh) * Nn + n;
        g_s1[o] = r1;
        g_s2[o] = r2;
    }
}

// ---------------------------------------------------------------------------
// t1/t2 output-layer scores (warp per row, 512-length dot)
// ---------------------------------------------------------------------------
__global__ __launch_bounds__(256) void t12_kernel(
    const float* __restrict__ a1, const float* __restrict__ a2)
{
    int gw = (blockIdx.x * blockDim.x + threadIdx.x) >> 5;
    int lane = threadIdx.x & 31;
    if (gw >= Bq * Nn) return;
    const float* row = g_Wx + (size_t)gw * HID;
    float r1 = 0.f, r2 = 0.f;
#pragma unroll
    for (int c0 = 0; c0 < HID; c0 += 128) {
        float4 v = *(const float4*)(row + c0 + lane * 4);
        float4 w1 = *(const float4*)(a1 + c0 + lane * 4);
        float4 w2 = *(const float4*)(a2 + c0 + lane * 4);
        r1 += v.x * w1.x + v.y * w1.y + v.z * w1.z + v.w * w1.w;
        r2 += v.x * w2.x + v.y * w2.y + v.z * w2.z + v.w * w2.w;
    }
#pragma unroll
    for (int o = 16; o; o >>= 1) {
        r1 += __shfl_xor_sync(0xffffffffu, r1, o);
        r2 += __shfl_xor_sync(0xffffffffu, r2, o);
    }
    if (lane == 0) { g_t1[gw] = r1; g_t2[gw] = r2; }
}

// ---------------------------------------------------------------------------
// attn1 (tf32 mma AV): block = (bh, half). 64 att rows.
// smem: sWh tf32 [128][72], sAtt tf32 [64][132], ss1[64], ss2[128].
// Bank checks: B-frag bank = (lc4*8 + lr4)%32 distinct; A-frag = lane distinct.
// ---------------------------------------------------------------------------
#define WH_STR 72
#define AT_STR 132

__global__ __launch_bounds__(256) void attn1_kernel(
    const float* __restrict__ ae_heads, const int* __restrict__ adj,
    const float* __restrict__ edge)
{
    extern __shared__ u32 smu[];
    u32* sWh  = smu;                       // 128*72
    u32* sAtt = smu + 128 * WH_STR;        // 64*132
    float* ss1 = (float*)(smu + 128 * WH_STR + 64 * AT_STR);   // 64
    float* ss2 = ss1 + 64;                                      // 128

    int tid = threadIdx.x;
    int blk = blockIdx.x;
    int hb = blk & 1;
    int bh = blk >> 1;
    int hh = bh & 7, b = bh >> 3;
    int i0 = hb * 64;
    float ae = ae_heads[hh];

    // load Wh tile [128 x 64] as tf32
    const float* whp = g_Wh + (size_t)b * Nn * HID + hh * NHID;
    for (int i = tid; i < 128 * 16; i += 256) {
        int r = i >> 4, c = (i & 15) * 4;
        float4 v = *(const float4*)(whp + (size_t)r * HID + c);
        uint4 t;
        t.x = to_tf32(v.x); t.y = to_tf32(v.y);
        t.z = to_tf32(v.z); t.w = to_tf32(v.w);
        *(uint4*)&sWh[r * WH_STR + c] = t;
    }
    if (tid < 64)  ss1[tid] = g_s1[bh * Nn + i0 + tid];
    if (tid < 128) ss2[tid] = g_s2[bh * Nn + tid];
    __syncthreads();

    int warp = tid >> 5, lane = tid & 31;
    // softmax rows -> sAtt (tf32)
    for (int i = warp; i < 64; i += 8) {
        int row = i0 + i;
        float4 ef = ((const float4*)(edge + ((size_t)b * Nn + row) * Nn))[lane];
        int4  av  = ((const int4*)(adj  + ((size_t)b * Nn + row) * Nn))[lane];
        float si = ss1[i];
        int j0 = lane * 4;
        float v0 = si + ss2[j0 + 0] + ef.x * ae; v0 = v0 >= 0.f ? v0 : 0.2f * v0; v0 = av.x > 0 ? v0 : -9e15f;
        float v1 = si + ss2[j0 + 1] + ef.y * ae; v1 = v1 >= 0.f ? v1 : 0.2f * v1; v1 = av.y > 0 ? v1 : -9e15f;
        float v2 = si + ss2[j0 + 2] + ef.z * ae; v2 = v2 >= 0.f ? v2 : 0.2f * v2; v2 = av.z > 0 ? v2 : -9e15f;
        float v3 = si + ss2[j0 + 3] + ef.w * ae; v3 = v3 >= 0.f ? v3 : 0.2f * v3; v3 = av.w > 0 ? v3 : -9e15f;
        float m = fmaxf(fmaxf(v0, v1), fmaxf(v2, v3));
#pragma unroll
        for (int o = 16; o; o >>= 1) m = fmaxf(m, __shfl_xor_sync(0xffffffffu, m, o));
        float e0 = __expf(v0 - m), e1 = __expf(v1 - m), e2 = __expf(v2 - m), e3 = __expf(v3 - m);
        float s = e0 + e1 + e2 + e3;
#pragma unroll
        for (int o = 16; o; o >>= 1) s += __shfl_xor_sync(0xffffffffu, s, o);
        float inv = 1.f / s;
        uint4 o4;
        o4.x = to_tf32(e0 * inv); o4.y = to_tf32(e1 * inv);
        o4.z = to_tf32(e2 * inv); o4.w = to_tf32(e3 * inv);
        *(uint4*)&sAtt[i * AT_STR + lane * 4] = o4;
    }
    __syncthreads();

    // D[64x64] = att[64x128] @ Wh[128x64] via mma
    int wr = warp >> 2, wc = warp & 3;     // 2 x 4; warp tile 32x16
    int lr4 = lane >> 2, lc4 = lane & 3;
    float acc[2][2][4];
#pragma unroll
    for (int mt = 0; mt < 2; mt++)
#pragma unroll
        for (int nt = 0; nt < 2; nt++)
#pragma unroll
            for (int i = 0; i < 4; i++) acc[mt][nt][i] = 0.f;

#pragma unroll
    for (int kk = 0; kk < 128; kk += 8) {
        u32 afr[2][4], bfr[2][2];
#pragma unroll
        for (int mt = 0; mt < 2; mt++) {
            int r0 = wr * 32 + mt * 16 + lr4;
            int c0 = kk + lc4;
            afr[mt][0] = sAtt[r0 * AT_STR + c0];
            afr[mt][1] = sAtt[(r0 + 8) * AT_STR + c0];
            afr[mt][2] = sAtt[r0 * AT_STR + c0 + 4];
            afr[mt][3] = sAtt[(r0 + 8) * AT_STR + c0 + 4];
        }
#pragma unroll
        for (int nt = 0; nt < 2; nt++) {
            int col = wc * 16 + nt * 8 + lr4;
            bfr[nt][0] = sWh[(kk + lc4) * WH_STR + col];
            bfr[nt][1] = sWh[(kk + lc4 + 4) * WH_STR + col];
        }
#pragma unroll
        for (int mt = 0; mt < 2; mt++)
#pragma unroll
            for (int nt = 0; nt < 2; nt++)
                mma_tf32(acc[mt][nt], afr[mt], bfr[nt]);
    }

    // ELU + store to g_x[b, i, hh*64 + col]
#pragma unroll
    for (int mt = 0; mt < 2; mt++)
#pragma unroll
        for (int nt = 0; nt < 2; nt++) {
            int col = wc * 16 + nt * 8 + lc4 * 2;
#pragma unroll
            for (int half = 0; half < 2; half++) {
                int i = i0 + wr * 32 + mt * 16 + lr4 + half * 8;
                float2 v;
                v.x = elu1(acc[mt][nt][half * 2]);
                v.y = elu1(acc[mt][nt][half * 2 + 1]);
                *(float2*)(g_x + ((size_t)b * Nn + i) * HID + hh * NHID + col) = v;
            }
        }
}

// ---------------------------------------------------------------------------
// attn2 (tf32 mma AV + ELU + column sums): block = (b, half).
// smem: sAtt tf32 [64][132], sWx tf32 [128][72], st1[64], st2[128], scratch[128]
// ---------------------------------------------------------------------------
__global__ __launch_bounds__(256) void attn2_kernel(
    const float* __restrict__ ae_out, const int* __restrict__ adj,
    const float* __restrict__ edge)
{
    extern __shared__ u32 smu[];
    u32* sAtt = smu;                       // 64*132
    u32* sWx  = smu + 64 * AT_STR;         // 128*72
    float* st1 = (float*)(smu + 64 * AT_STR + 128 * WH_STR);  // 64
    float* st2 = st1 + 64;                                     // 128
    float* scratch = st2 + 128;                                // 128 (2 x 64)

    int tid = threadIdx.x;
    int blk = blockIdx.x;
    int hb = blk & 1;
    int b = blk >> 1;
    int i0 = hb * 64;
    float ae = ae_out[0];

    if (tid < 64)  st1[tid] = g_t1[b * Nn + i0 + tid];
    if (tid < 128) st2[tid] = g_t2[b * Nn + tid];
    __syncthreads();

    int warp = tid >> 5, lane = tid & 31;
    for (int i = warp; i < 64; i += 8) {
        int row = i0 + i;
        float4 ef = ((const float4*)(edge + ((size_t)b * Nn + row) * Nn))[lane];
        int4  av  = ((const int4*)(adj  + ((size_t)b * Nn + row) * Nn))[lane];
        float si = st1[i];
        int j0 = lane * 4;
        float v0 = si + st2[j0 + 0] + ef.x * ae; v0 = v0 >= 0.f ? v0 : 0.2f * v0; v0 = av.x > 0 ? v0 : -9e15f;
        float v1 = si + st2[j0 + 1] + ef.y * ae; v1 = v1 >= 0.f ? v1 : 0.2f * v1; v1 = av.y > 0 ? v1 : -9e15f;
        float v2 = si + st2[j0 + 2] + ef.z * ae; v2 = v2 >= 0.f ? v2 : 0.2f * v2; v2 = av.z > 0 ? v2 : -9e15f;
        float v3 = si + st2[j0 + 3] + ef.w * ae; v3 = v3 >= 0.f ? v3 : 0.2f * v3; v3 = av.w > 0 ? v3 : -9e15f;
        float m = fmaxf(fmaxf(v0, v1), fmaxf(v2, v3));
#pragma unroll
        for (int o = 16; o; o >>= 1) m = fmaxf(m, __shfl_xor_sync(0xffffffffu, m, o));
        float e0 = __expf(v0 - m), e1 = __expf(v1 - m), e2 = __expf(v2 - m), e3 = __expf(v3 - m);
        float s = e0 + e1 + e2 + e3;
#pragma unroll
        for (int o = 16; o; o >>= 1) s += __shfl_xor_sync(0xffffffffu, s, o);
        float inv = 1.f / s;
        uint4 o4;
        o4.x = to_tf32(e0 * inv); o4.y = to_tf32(e1 * inv);
        o4.z = to_tf32(e2 * inv); o4.w = to_tf32(e3 * inv);
        *(uint4*)&sAtt[i * AT_STR + lane * 4] = o4;
    }
    __syncthreads();

    int wr = warp >> 2, wc = warp & 3;
    int lr4 = lane >> 2, lc4 = lane & 3;

    for (int ch = 0; ch < 8; ch++) {
        // load Wx chunk [128 x 64] as tf32
        const float* wp = g_Wx + (size_t)b * Nn * HID + ch * 64;
        for (int i = tid; i < 128 * 16; i += 256) {
            int r = i >> 4, c = (i & 15) * 4;
            float4 v = *(const float4*)(wp + (size_t)r * HID + c);
            uint4 t;
            t.x = to_tf32(v.x); t.y = to_tf32(v.y);
            t.z = to_tf32(v.z); t.w = to_tf32(v.w);
            *(uint4*)&sWx[r * WH_STR + c] = t;
        }
        __syncthreads();

        float acc[2][2][4];
#pragma unroll
        for (int mt = 0; mt < 2; mt++)
#pragma unroll
            for (int nt = 0; nt < 2; nt++)
#pragma unroll
                for (int i = 0; i < 4; i++) acc[mt][nt][i] = 0.f;

#pragma unroll
        for (int kk = 0; kk < 128; kk += 8) {
            u32 afr[2][4], bfr[2][2];
#pragma unroll
            for (int mt = 0; mt < 2; mt++) {
                int r0 = wr * 32 + mt * 16 + lr4;
                int c0 = kk + lc4;
                afr[mt][0] = sAtt[r0 * AT_STR + c0];
                afr[mt][1] = sAtt[(r0 + 8) * AT_STR + c0];
                afr[mt][2] = sAtt[r0 * AT_STR + c0 + 4];
                afr[mt][3] = sAtt[(r0 + 8) * AT_STR + c0 + 4];
            }
#pragma unroll
            for (int nt = 0; nt < 2; nt++) {
                int col = wc * 16 + nt * 8 + lr4;
                bfr[nt][0] = sWx[(kk + lc4) * WH_STR + col];
                bfr[nt][1] = sWx[(kk + lc4 + 4) * WH_STR + col];
            }
#pragma unroll
            for (int mt = 0; mt < 2; mt++)
#pragma unroll
                for (int nt = 0; nt < 2; nt++)
                    mma_tf32(acc[mt][nt], afr[mt], bfr[nt]);
        }

        // ELU + per-thread column sums over this thread's 4 rows
        float cs[2][2];
#pragma unroll
        for (int nt = 0; nt < 2; nt++) {
            cs[nt][0] = 0.f; cs[nt][1] = 0.f;
#pragma unroll
            for (int mt = 0; mt < 2; mt++) {
                cs[nt][0] += elu1(acc[mt][nt][0]) + elu1(acc[mt][nt][2]);
                cs[nt][1] += elu1(acc[mt][nt][1]) + elu1(acc[mt][nt][3]);
            }
        }
        // reduce over lr4 (8 lanes, xor offsets 4, 8, 16)
#pragma unroll
        for (int o = 4; o <= 16; o <<= 1) {
#pragma unroll
            for (int nt = 0; nt < 2; nt++) {
                cs[nt][0] += __shfl_xor_sync(0xffffffffu, cs[nt][0], o);
                cs[nt][1] += __shfl_xor_sync(0xffffffffu, cs[nt][1], o);
            }
        }
        if (lr4 == 0) {
#pragma unroll
            for (int nt = 0; nt < 2; nt++) {
                int col = wc * 16 + nt * 8 + lc4 * 2;
                scratch[wr * 64 + col]     = cs[nt][0];
                scratch[wr * 64 + col + 1] = cs[nt][1];
            }
        }
        __syncthreads();
        if (tid < 64)
            g_gatp[((size_t)b * 2 + hb) * HID + ch * 64 + tid] =
                scratch[tid] + scratch[64 + tid];
        __syncthreads();
    }
}

// ---------------------------------------------------------------------------
__global__ void gat_reduce_kernel()
{
    int idx = blockIdx.x * blockDim.x + threadIdx.x;
    if (idx >= Bq * HID) return;
    int b = idx >> 9, c = idx & 511;
    g_gat[idx] = (g_gatp[((size_t)b * 2) * HID + c] +
                  g_gatp[((size_t)b * 2 + 1) * HID + c]) * (1.f / 128.f);
}

// ---------------------------------------------------------------------------
__global__ void final_kernel(const float* __restrict__ X,
                             const float* __restrict__ W,
                             const float* __restrict__ bias,
                             float* __restrict__ out)
{
    int idx = blockIdx.x * blockDim.x + threadIdx.x;
    if (idx >= Bq * TASKS) return;
    int b = idx / TASKS, t = idx - b * TASKS;
    const float* x = X + (size_t)b * HID;
    float s = bias[t];
    for (int d = 0; d < HID; d++) s += x[d] * W[d * TASKS + t];
    out[idx] = s;
}

// ---------------------------------------------------------------------------
extern "C" void kernel_launch(void* const* d_in, const int* in_sizes, int n_in,
                              void* d_out, int out_size)
{
    const float* h        = (const float*)d_in[0];
    const int*   adj      = (const int*)d_in[1];
    const float* edge     = (const float*)d_in[2];
    const float* fp       = (const float*)d_in[3];
    const float* W_heads  = (const float*)d_in[4];
    const float* a1_heads = (const float*)d_in[5];
    const float* a2_heads = (const float*)d_in[6];
    const float* ae_heads = (const float*)d_in[7];
    const float* W_out    = (const float*)d_in[8];
    const float* a1_out   = (const float*)d_in[9];
    const float* a2_out   = (const float*)d_in[10];
    const float* ae_out   = (const float*)d_in[11];
    const float* fc1_w    = (const float*)d_in[12];
    const float* fc1_b    = (const float*)d_in[13];
    const float* fc2_w    = (const float*)d_in[14];
    const float* fc2_b    = (const float*)d_in[15];
    const float* q_w      = (const float*)d_in[16];
    const float* q_b      = (const float*)d_in[17];
    // k_w (18), k_b (19) unused: softmax over size-1 axis == 1 -> fused = q+v
    const float* v_w      = (const float*)d_in[20];
    const float* v_b      = (const float*)d_in[21];
    const float* o_w      = (const float*)d_in[22];
    const float* o_b      = (const float*)d_in[23];
    const float* ffn1_w   = (const float*)d_in[24];
    const float* ffn1_b   = (const float*)d_in[25];
    const float* ffn2_w   = (const float*)d_in[26];
    const float* ffn2_b   = (const float*)d_in[27];
    float* out = (float*)d_out;

    float *Wh, *x, *gat, *fpnh, *fpn, *buf1, *buf2, *Wx, *Wcat;
    cudaGetSymbolAddress((void**)&Wh, g_Wh);
    cudaGetSymbolAddress((void**)&x, g_x);
    cudaGetSymbolAddress((void**)&Wx, g_Wx);
    cudaGetSymbolAddress((void**)&gat, g_gat);
    cudaGetSymbolAddress((void**)&fpnh, g_fpnh);
    cudaGetSymbolAddress((void**)&fpn, g_fpn);
    cudaGetSymbolAddress((void**)&buf1, g_buf1);
    cudaGetSymbolAddress((void**)&buf2, g_buf2);
    cudaGetSymbolAddress((void**)&Wcat, g_Wcat);

    // smem: attn1 = 128*72 + 64*132 + 192 floats; attn2 = same + 128 scratch
    const int ATT1_SMEM = (128 * WH_STR + 64 * AT_STR + 192) * 4;          // 71424
    const int ATT2_SMEM = (64 * AT_STR + 128 * WH_STR + 320) * 4;          // 71936
    cudaFuncSetAttribute(attn1_kernel, cudaFuncAttributeMaxDynamicSharedMemorySize, ATT1_SMEM);
    cudaFuncSetAttribute(attn2_kernel, cudaFuncAttributeMaxDynamicSharedMemorySize, ATT2_SMEM);

    const int M1 = Bq * Nn;  // 65536

    // 1. Wcat transpose
    wcat_kernel<<<(NHEADS * F_IN * NHID + 255) / 256, 256>>>(W_heads);

    // 2. Wh = h @ Wcat  (fast tf32)
    {
        dim3 grid(HID / 128, M1 / 128);
        sgemm_tc_kernel<<<grid, 256>>>(h, Wcat, nullptr, Wh, M1, HID, F_IN, 0);
    }

    // 3. s1/s2
    s12_kernel<<<(Bq * NHEADS * Nn * 32) / 256, 256>>>(a1_heads, a2_heads);

    // 4. attn1 (tf32 mma)
    attn1_kernel<<<Bq * NHEADS * 2, 256, ATT1_SMEM>>>(ae_heads, adj, edge);

    // 5. Wx = x @ W_out (fast tf32)
    {
        dim3 grid(HID / 128, M1 / 128);
        sgemm_tc_kernel<<<grid, 256>>>(x, W_out, nullptr, Wx, M1, HID, HID, 0);
    }

    // 6. t1/t2
    t12_kernel<<<(Bq * Nn * 32) / 256, 256>>>(a1_out, a2_out);

    // 7. attn2 (tf32 mma) + mean reduce
    attn2_kernel<<<Bq * 2, 256, ATT2_SMEM>>>(ae_out, adj, edge);
    gat_reduce_kernel<<<(Bq * HID + 255) / 256, 256>>>();

    // 8. FPN (precise 3x tf32)
    {
        dim3 grid(HID / 128, Bq / 128);
        sgemm_tc3_kernel<<<grid, 256>>>(fp, fc1_w, fc1_b, fpnh, Bq, HID, FP_DIM, 1 | 2);
        sgemm_tc3_kernel<<<grid, 256>>>(fpnh, fc2_w, fc2_b, fpn, Bq, HID, HID, 1);
    }

    // 9. fusion + FFN (precise 3x tf32)
    {
        dim3 grid(HID / 128, Bq / 128);
        sgemm_tc3_kernel<<<grid, 256>>>(gat, q_w, q_b, buf1, Bq, HID, HID, 1);
        sgemm_tc3_kernel<<<grid, 256>>>(fpn, v_w, v_b, buf1, Bq, HID, HID, 1 | 4);
        sgemm_tc3_kernel<<<grid, 256>>>(buf1, o_w, o_b, buf2, Bq, HID, HID, 1 | 2);
        sgemm_tc3_kernel<<<grid, 256>>>(buf2, ffn1_w, ffn1_b, buf1, Bq, HID, HID, 1 | 2);
    }

    // 10. final projection
    final_kernel<<<(Bq * TASKS + 255) / 256, 256>>>(buf1, ffn2_w, ffn2_b, out);
}

// round 10
// speedup vs baseline: 1.2762x; 1.2762x over previous
#include <cuda_runtime.h>
#include <cuda_bf16.h>
#include <math.h>

// ---------------------------------------------------------------------------
// FPGNN forward. R10:
//  - big GEMMs (Wh, Wx): 1x tf32 mma.sync (fast path)
//  - attn1/attn2 AV products: tf32 mma.sync on smem tiles
//  - tail GEMMs (fc1, fc2, q, v, o, ffn1): fp32 FFMA2 SIMT, 64x64 tiles
//    (exact; grid 64 CTAs instead of 16 -> latency-bound fix)
// ---------------------------------------------------------------------------

#define Bq 512
#define Nn 128
#define F_IN 133
#define NHEADS 8
#define NHID 64
#define HID 512
#define FP_DIM 1489
#define TASKS 12

typedef unsigned long long u64;
typedef unsigned int u32;

__device__ __forceinline__ u64 pack2(float lo, float hi) {
    u64 r; asm("mov.b64 %0, {%1,%2};" : "=l"(r) : "f"(lo), "f"(hi)); return r;
}
__device__ __forceinline__ u64 dup2(float v) { return pack2(v, v); }
__device__ __forceinline__ void fma2(u64& d, u64 a, u64 b) {
    asm("fma.rn.f32x2 %0, %1, %2, %0;" : "+l"(d) : "l"(a), "l"(b));
}
__device__ __forceinline__ float2 upk2(u64 v) {
    float2 r; asm("mov.b64 {%0,%1}, %2;" : "=f"(r.x), "=f"(r.y) : "l"(v)); return r;
}
__device__ __forceinline__ u32 to_tf32(float f) {
    u32 r; asm("cvt.rna.tf32.f32 %0, %1;" : "=r"(r) : "f"(f)); return r;
}
__device__ __forceinline__ void mma_tf32(float* d, const u32* a, const u32* b) {
    asm volatile(
        "mma.sync.aligned.m16n8k8.row.col.f32.tf32.tf32.f32 "
        "{%0,%1,%2,%3}, {%4,%5,%6,%7}, {%8,%9}, {%0,%1,%2,%3};\n"
        : "+f"(d[0]), "+f"(d[1]), "+f"(d[2]), "+f"(d[3])
        : "r"(a[0]), "r"(a[1]), "r"(a[2]), "r"(a[3]), "r"(b[0]), "r"(b[1]));
}
__device__ __forceinline__ float elu1(float v) {
    return v > 0.f ? v : (__expf(v) - 1.f);
}

// ---- scratch (device globals; no allocation allowed) ----
__device__ float g_Wcat[F_IN * HID];
__device__ float g_Wh[(size_t)Bq * Nn * HID];
__device__ float g_s1[Bq * NHEADS * Nn];
__device__ float g_s2[Bq * NHEADS * Nn];
__device__ float g_x[(size_t)Bq * Nn * HID];
__device__ float g_Wx[(size_t)Bq * Nn * HID];
__device__ float g_t1[Bq * Nn];
__device__ float g_t2[Bq * Nn];
__device__ float g_gatp[Bq * 2 * HID];
__device__ float g_gat[Bq * HID];
__device__ float g_fpnh[Bq * HID];
__device__ float g_fpn[Bq * HID];
__device__ float g_buf1[Bq * HID];
__device__ float g_buf2[Bq * HID];

// ---------------------------------------------------------------------------
// 1x tf32 GEMM (fast path, big GEMMs). Validated R8.
// flags: 1 = bias, 2 = relu, 4 = accumulate
// ---------------------------------------------------------------------------
#define SA_STRIDE 20
#define SB_STRIDE 136

__global__ __launch_bounds__(256) void sgemm_tc_kernel(
    const float* __restrict__ A, const float* __restrict__ B,
    const float* __restrict__ bias, float* __restrict__ C,
    int M, int N, int K, int flags)
{
    __shared__ u32 sA[2][128 * SA_STRIDE];
    __shared__ u32 sB[2][16 * SB_STRIDE];

    int tid = threadIdx.x;
    int warp = tid >> 5, lane = tid & 31;
    int wr = warp >> 2, wc = warp & 3;
    int bm = blockIdx.y * 128;
    int bn = blockIdx.x * 128;
    int lr4 = lane >> 2, lc4 = lane & 3;

    float acc[4][4][4];
#pragma unroll
    for (int mt = 0; mt < 4; mt++)
#pragma unroll
        for (int nt = 0; nt < 4; nt++)
#pragma unroll
            for (int i = 0; i < 4; i++) acc[mt][nt][i] = 0.f;

    const int Ktiles = (K + 15) / 16;
    int aRow0 = tid >> 2,         aK0 = (tid & 3) * 4;
    int aRow1 = (tid + 256) >> 2, aK1 = ((tid + 256) & 3) * 4;
    int bK0 = tid >> 5,           bN0 = (tid & 31) * 4;
    int bK1 = (tid + 256) >> 5,   bN1 = ((tid + 256) & 31) * 4;

    float ar[2][4], br[2][4];
    {
#pragma unroll
        for (int i = 0; i < 4; i++) {
            int k = aK0 + i;
            ar[0][i] = (k < K) ? A[(size_t)(bm + aRow0) * K + k] : 0.f;
            k = aK1 + i;
            ar[1][i] = (k < K) ? A[(size_t)(bm + aRow1) * K + k] : 0.f;
        }
        if (bK0 < K) *(float4*)br[0] = *(const float4*)(B + (size_t)bK0 * N + bn + bN0);
        else { br[0][0] = br[0][1] = br[0][2] = br[0][3] = 0.f; }
        if (bK1 < K) *(float4*)br[1] = *(const float4*)(B + (size_t)bK1 * N + bn + bN1);
        else { br[1][0] = br[1][1] = br[1][2] = br[1][3] = 0.f; }
    }
#pragma unroll
    for (int i = 0; i < 4; i++) {
        sA[0][aRow0 * SA_STRIDE + aK0 + i] = to_tf32(ar[0][i]);
        sA[0][aRow1 * SA_STRIDE + aK1 + i] = to_tf32(ar[1][i]);
        sB[0][bK0 * SB_STRIDE + bN0 + i] = to_tf32(br[0][i]);
        sB[0][bK1 * SB_STRIDE + bN1 + i] = to_tf32(br[1][i]);
    }
    __syncthreads();

    int buf = 0;
    for (int t = 0; t < Ktiles; t++) {
        bool has_next = (t + 1 < Ktiles);
        if (has_next) {
            int k0 = (t + 1) * 16;
#pragma unroll
            for (int i = 0; i < 4; i++) {
                int k = k0 + aK0 + i;
                ar[0][i] = (k < K) ? A[(size_t)(bm + aRow0) * K + k] : 0.f;
                k = k0 + aK1 + i;
                ar[1][i] = (k < K) ? A[(size_t)(bm + aRow1) * K + k] : 0.f;
            }
            int k = k0 + bK0;
            if (k < K) *(float4*)br[0] = *(const float4*)(B + (size_t)k * N + bn + bN0);
            else { br[0][0] = br[0][1] = br[0][2] = br[0][3] = 0.f; }
            k = k0 + bK1;
            if (k < K) *(float4*)br[1] = *(const float4*)(B + (size_t)k * N + bn + bN1);
            else { br[1][0] = br[1][1] = br[1][2] = br[1][3] = 0.f; }
        }

        const u32* cA = sA[buf];
        const u32* cB = sB[buf];
#pragma unroll
        for (int kk = 0; kk < 16; kk += 8) {
            u32 afr[4][4], bfr[4][2];
#pragma unroll
            for (int mt = 0; mt < 4; mt++) {
                int r0 = wr * 64 + mt * 16 + lr4;
                int c0 = kk + lc4;
                afr[mt][0] = cA[r0 * SA_STRIDE + c0];
                afr[mt][1] = cA[(r0 + 8) * SA_STRIDE + c0];
                afr[mt][2] = cA[r0 * SA_STRIDE + c0 + 4];
                afr[mt][3] = cA[(r0 + 8) * SA_STRIDE + c0 + 4];
            }
#pragma unroll
            for (int nt = 0; nt < 4; nt++) {
                int col = wc * 32 + nt * 8 + lr4;
                bfr[nt][0] = cB[(kk + lc4) * SB_STRIDE + col];
                bfr[nt][1] = cB[(kk + lc4 + 4) * SB_STRIDE + col];
            }
#pragma unroll
            for (int mt = 0; mt < 4; mt++)
#pragma unroll
                for (int nt = 0; nt < 4; nt++)
                    mma_tf32(acc[mt][nt], afr[mt], bfr[nt]);
        }

        if (has_next) {
#pragma unroll
            for (int i = 0; i < 4; i++) {
                sA[buf ^ 1][aRow0 * SA_STRIDE + aK0 + i] = to_tf32(ar[0][i]);
                sA[buf ^ 1][aRow1 * SA_STRIDE + aK1 + i] = to_tf32(ar[1][i]);
                sB[buf ^ 1][bK0 * SB_STRIDE + bN0 + i] = to_tf32(br[0][i]);
                sB[buf ^ 1][bK1 * SB_STRIDE + bN1 + i] = to_tf32(br[1][i]);
            }
        }
        __syncthreads();
        buf ^= 1;
    }

#pragma unroll
    for (int mt = 0; mt < 4; mt++) {
#pragma unroll
        for (int nt = 0; nt < 4; nt++) {
            int col = bn + wc * 32 + nt * 8 + lc4 * 2;
#pragma unroll
            for (int half = 0; half < 2; half++) {
                int row = bm + wr * 64 + mt * 16 + lr4 + half * 8;
                float2 v = make_float2(acc[mt][nt][half * 2],
                                       acc[mt][nt][half * 2 + 1]);
                if (flags & 4) {
                    float2 c = *(const float2*)&C[(size_t)row * N + col];
                    v.x += c.x; v.y += c.y;
                }
                if (flags & 1) { v.x += bias[col]; v.y += bias[col + 1]; }
                if (flags & 2) { v.x = fmaxf(v.x, 0.f); v.y = fmaxf(v.y, 0.f); }
                *(float2*)&C[(size_t)row * N + col] = v;
            }
        }
    }
}

// ---------------------------------------------------------------------------
// Tail fp32 GEMM (exact): BM=BN=64, BK=16, 256 threads, 4x4 per-thread tile
// (FFMA2), double-buffered. Grid (N/64, M/64). M%64==0, N%64==0 required.
// flags: 1 = bias, 2 = relu, 4 = accumulate
// ---------------------------------------------------------------------------
__global__ __launch_bounds__(256) void tail_gemm_kernel(
    const float* __restrict__ A, const float* __restrict__ B,
    const float* __restrict__ bias, float* __restrict__ C,
    int M, int N, int K, int flags)
{
    __shared__ float As[2][16][64];   // [k][m]
    __shared__ float Bs[2][16][64];   // [k][n]

    int tid = threadIdx.x;
    int bm = blockIdx.y * 64;
    int bn = blockIdx.x * 64;
    int tx = tid & 15;      // cols tx*4..+3
    int ty = tid >> 4;      // rows ty*4..+3

    // A loads: thread -> row = tid>>2 (0..63), kseg = (tid&3)*4
    int aRow = tid >> 2, aK = (tid & 3) * 4;
    // B loads: thread -> k = tid>>4 (0..15), nseg = (tid&15)*4
    int bK = tid >> 4, bN = (tid & 15) * 4;

    u64 acc[4][2];
#pragma unroll
    for (int i = 0; i < 4; i++) { acc[i][0] = 0ull; acc[i][1] = 0ull; }

    const int Ktiles = (K + 15) / 16;
    const float* Arow = A + (size_t)(bm + aRow) * K;

    // preload tile 0
    {
#pragma unroll
        for (int i = 0; i < 4; i++) {
            int k = aK + i;
            As[0][aK + i][aRow] = (k < K) ? Arow[k] : 0.f;
        }
        float4 v = make_float4(0.f, 0.f, 0.f, 0.f);
        if (bK < K) v = *(const float4*)(B + (size_t)bK * N + bn + bN);
        *(float4*)&Bs[0][bK][bN] = v;
    }
    __syncthreads();

    int buf = 0;
    for (int t = 0; t < Ktiles; t++) {
        float ap[4];
        float4 bp = make_float4(0.f, 0.f, 0.f, 0.f);
        bool has_next = (t + 1 < Ktiles);
        if (has_next) {
            int k0 = (t + 1) * 16;
#pragma unroll
            for (int i = 0; i < 4; i++) {
                int k = k0 + aK + i;
                ap[i] = (k < K) ? Arow[k] : 0.f;
            }
            int k = k0 + bK;
            if (k < K) bp = *(const float4*)(B + (size_t)k * N + bn + bN);
        }

#pragma unroll
        for (int kk = 0; kk < 16; kk++) {
            u64 b0 = *(const u64*)&Bs[buf][kk][tx * 4];
            u64 b1 = *(const u64*)&Bs[buf][kk][tx * 4 + 2];
            float a0 = As[buf][kk][ty * 4];
            float a1 = As[buf][kk][ty * 4 + 1];
            float a2 = As[buf][kk][ty * 4 + 2];
            float a3 = As[buf][kk][ty * 4 + 3];
            u64 d0 = dup2(a0), d1 = dup2(a1), d2 = dup2(a2), d3 = dup2(a3);
            fma2(acc[0][0], d0, b0); fma2(acc[0][1], d0, b1);
            fma2(acc[1][0], d1, b0); fma2(acc[1][1], d1, b1);
            fma2(acc[2][0], d2, b0); fma2(acc[2][1], d2, b1);
            fma2(acc[3][0], d3, b0); fma2(acc[3][1], d3, b1);
        }

        if (has_next) {
#pragma unroll
            for (int i = 0; i < 4; i++) As[buf ^ 1][aK + i][aRow] = ap[i];
            *(float4*)&Bs[buf ^ 1][bK][bN] = bp;
        }
        __syncthreads();
        buf ^= 1;
    }

#pragma unroll
    for (int i = 0; i < 4; i++) {
        int row = bm + ty * 4 + i;
#pragma unroll
        for (int j = 0; j < 2; j++) {
            int col = bn + tx * 4 + j * 2;
            float2 v = upk2(acc[i][j]);
            if (flags & 4) {
                float2 c = *(const float2*)&C[(size_t)row * N + col];
                v.x += c.x; v.y += c.y;
            }
            if (flags & 1) { v.x += bias[col]; v.y += bias[col + 1]; }
            if (flags & 2) { v.x = fmaxf(v.x, 0.f); v.y = fmaxf(v.y, 0.f); }
            *(float2*)&C[(size_t)row * N + col] = v;
        }
    }
}

// ---------------------------------------------------------------------------
// W_heads [8,133,64] -> Wcat [133, 512]
// ---------------------------------------------------------------------------
__global__ void wcat_kernel(const float* __restrict__ W_heads)
{
    int idx = blockIdx.x * blockDim.x + threadIdx.x;
    if (idx >= NHEADS * F_IN * NHID) return;
    int h = idx / (F_IN * NHID);
    int rem = idx - h * (F_IN * NHID);
    int f = rem / NHID;
    int d = rem - f * NHID;
    g_Wcat[f * HID + h * NHID + d] = W_heads[idx];
}

// ---------------------------------------------------------------------------
// s1/s2 head scores (warp per row, 64-length dot)
// ---------------------------------------------------------------------------
__global__ __launch_bounds__(256) void s12_kernel(
    const float* __restrict__ a1, const float* __restrict__ a2)
{
    int gw = (blockIdx.x * blockDim.x + threadIdx.x) >> 5;
    int lane = threadIdx.x & 31;
    if (gw >= Bq * NHEADS * Nn) return;
    int n  = gw & 127;
    int hh = (gw >> 7) & 7;
    int b  = gw >> 10;
    const float* row = g_Wh + ((size_t)b * Nn + n) * HID + hh * NHID;
    const float* av1 = a1 + hh * NHID;
    const float* av2 = a2 + hh * NHID;
    float x0 = row[lane], x1 = row[lane + 32];
    float r1 = x0 * av1[lane] + x1 * av1[lane + 32];
    float r2 = x0 * av2[lane] + x1 * av2[lane + 32];
#pragma unroll
    for (int o = 16; o; o >>= 1) {
        r1 += __shfl_xor_sync(0xffffffffu, r1, o);
        r2 += __shfl_xor_sync(0xffffffffu, r2, o);
    }
    if (lane == 0) {
        int o = (b * NHEADS + hh) * Nn + n;
        g_s1[o] = r1;
        g_s2[o] = r2;
    }
}

// ---------------------------------------------------------------------------
// t1/t2 output-layer scores (warp per row, 512-length dot)
// ---------------------------------------------------------------------------
__global__ __launch_bounds__(256) void t12_kernel(
    const float* __restrict__ a1, const float* __restrict__ a2)
{
    int gw = (blockIdx.x * blockDim.x + threadIdx.x) >> 5;
    int lane = threadIdx.x & 31;
    if (gw >= Bq * Nn) return;
    const float* row = g_Wx + (size_t)gw * HID;
    float r1 = 0.f, r2 = 0.f;
#pragma unroll
    for (int c0 = 0; c0 < HID; c0 += 128) {
        float4 v = *(const float4*)(row + c0 + lane * 4);
        float4 w1 = *(const float4*)(a1 + c0 + lane * 4);
        float4 w2 = *(const float4*)(a2 + c0 + lane * 4);
        r1 += v.x * w1.x + v.y * w1.y + v.z * w1.z + v.w * w1.w;
        r2 += v.x * w2.x + v.y * w2.y + v.z * w2.z + v.w * w2.w;
    }
#pragma unroll
    for (int o = 16; o; o >>= 1) {
        r1 += __shfl_xor_sync(0xffffffffu, r1, o);
        r2 += __shfl_xor_sync(0xffffffffu, r2, o);
    }
    if (lane == 0) { g_t1[gw] = r1; g_t2[gw] = r2; }
}

// ---------------------------------------------------------------------------
// attn1 (tf32 mma AV): block = (bh, half). 64 att rows. Validated R9.
// ---------------------------------------------------------------------------
#define WH_STR 72
#define AT_STR 132

__global__ __launch_bounds__(256) void attn1_kernel(
    const float* __restrict__ ae_heads, const int* __restrict__ adj,
    const float* __restrict__ edge)
{
    extern __shared__ u32 smu[];
    u32* sWh  = smu;                       // 128*72
    u32* sAtt = smu + 128 * WH_STR;        // 64*132
    float* ss1 = (float*)(smu + 128 * WH_STR + 64 * AT_STR);   // 64
    float* ss2 = ss1 + 64;                                      // 128

    int tid = threadIdx.x;
    int blk = blockIdx.x;
    int hb = blk & 1;
    int bh = blk >> 1;
    int hh = bh & 7, b = bh >> 3;
    int i0 = hb * 64;
    float ae = ae_heads[hh];

    const float* whp = g_Wh + (size_t)b * Nn * HID + hh * NHID;
    for (int i = tid; i < 128 * 16; i += 256) {
        int r = i >> 4, c = (i & 15) * 4;
        float4 v = *(const float4*)(whp + (size_t)r * HID + c);
        uint4 t;
        t.x = to_tf32(v.x); t.y = to_tf32(v.y);
        t.z = to_tf32(v.z); t.w = to_tf32(v.w);
        *(uint4*)&sWh[r * WH_STR + c] = t;
    }
    if (tid < 64)  ss1[tid] = g_s1[bh * Nn + i0 + tid];
    if (tid < 128) ss2[tid] = g_s2[bh * Nn + tid];
    __syncthreads();

    int warp = tid >> 5, lane = tid & 31;
    for (int i = warp; i < 64; i += 8) {
        int row = i0 + i;
        float4 ef = ((const float4*)(edge + ((size_t)b * Nn + row) * Nn))[lane];
        int4  av  = ((const int4*)(adj  + ((size_t)b * Nn + row) * Nn))[lane];
        float si = ss1[i];
        int j0 = lane * 4;
        float v0 = si + ss2[j0 + 0] + ef.x * ae; v0 = v0 >= 0.f ? v0 : 0.2f * v0; v0 = av.x > 0 ? v0 : -9e15f;
        float v1 = si + ss2[j0 + 1] + ef.y * ae; v1 = v1 >= 0.f ? v1 : 0.2f * v1; v1 = av.y > 0 ? v1 : -9e15f;
        float v2 = si + ss2[j0 + 2] + ef.z * ae; v2 = v2 >= 0.f ? v2 : 0.2f * v2; v2 = av.z > 0 ? v2 : -9e15f;
        float v3 = si + ss2[j0 + 3] + ef.w * ae; v3 = v3 >= 0.f ? v3 : 0.2f * v3; v3 = av.w > 0 ? v3 : -9e15f;
        float m = fmaxf(fmaxf(v0, v1), fmaxf(v2, v3));
#pragma unroll
        for (int o = 16; o; o >>= 1) m = fmaxf(m, __shfl_xor_sync(0xffffffffu, m, o));
        float e0 = __expf(v0 - m), e1 = __expf(v1 - m), e2 = __expf(v2 - m), e3 = __expf(v3 - m);
        float s = e0 + e1 + e2 + e3;
#pragma unroll
        for (int o = 16; o; o >>= 1) s += __shfl_xor_sync(0xffffffffu, s, o);
        float inv = 1.f / s;
        uint4 o4;
        o4.x = to_tf32(e0 * inv); o4.y = to_tf32(e1 * inv);
        o4.z = to_tf32(e2 * inv); o4.w = to_tf32(e3 * inv);
        *(uint4*)&sAtt[i * AT_STR + lane * 4] = o4;
    }
    __syncthreads();

    int wr = warp >> 2, wc = warp & 3;
    int lr4 = lane >> 2, lc4 = lane & 3;
    float acc[2][2][4];
#pragma unroll
    for (int mt = 0; mt < 2; mt++)
#pragma unroll
        for (int nt = 0; nt < 2; nt++)
#pragma unroll
            for (int i = 0; i < 4; i++) acc[mt][nt][i] = 0.f;

#pragma unroll
    for (int kk = 0; kk < 128; kk += 8) {
        u32 afr[2][4], bfr[2][2];
#pragma unroll
        for (int mt = 0; mt < 2; mt++) {
            int r0 = wr * 32 + mt * 16 + lr4;
            int c0 = kk + lc4;
            afr[mt][0] = sAtt[r0 * AT_STR + c0];
            afr[mt][1] = sAtt[(r0 + 8) * AT_STR + c0];
            afr[mt][2] = sAtt[r0 * AT_STR + c0 + 4];
            afr[mt][3] = sAtt[(r0 + 8) * AT_STR + c0 + 4];
        }
#pragma unroll
        for (int nt = 0; nt < 2; nt++) {
            int col = wc * 16 + nt * 8 + lr4;
            bfr[nt][0] = sWh[(kk + lc4) * WH_STR + col];
            bfr[nt][1] = sWh[(kk + lc4 + 4) * WH_STR + col];
        }
#pragma unroll
        for (int mt = 0; mt < 2; mt++)
#pragma unroll
            for (int nt = 0; nt < 2; nt++)
                mma_tf32(acc[mt][nt], afr[mt], bfr[nt]);
    }

#pragma unroll
    for (int mt = 0; mt < 2; mt++)
#pragma unroll
        for (int nt = 0; nt < 2; nt++) {
            int col = wc * 16 + nt * 8 + lc4 * 2;
#pragma unroll
            for (int half = 0; half < 2; half++) {
                int i = i0 + wr * 32 + mt * 16 + lr4 + half * 8;
                float2 v;
                v.x = elu1(acc[mt][nt][half * 2]);
                v.y = elu1(acc[mt][nt][half * 2 + 1]);
                *(float2*)(g_x + ((size_t)b * Nn + i) * HID + hh * NHID + col) = v;
            }
        }
}

// ---------------------------------------------------------------------------
// attn2 (tf32 mma AV + ELU + column sums): block = (b, half). Validated R9.
// ---------------------------------------------------------------------------
__global__ __launch_bounds__(256) void attn2_kernel(
    const float* __restrict__ ae_out, const int* __restrict__ adj,
    const float* __restrict__ edge)
{
    extern __shared__ u32 smu[];
    u32* sAtt = smu;                       // 64*132
    u32* sWx  = smu + 64 * AT_STR;         // 128*72
    float* st1 = (float*)(smu + 64 * AT_STR + 128 * WH_STR);  // 64
    float* st2 = st1 + 64;                                     // 128
    float* scratch = st2 + 128;                                // 128

    int tid = threadIdx.x;
    int blk = blockIdx.x;
    int hb = blk & 1;
    int b = blk >> 1;
    int i0 = hb * 64;
    float ae = ae_out[0];

    if (tid < 64)  st1[tid] = g_t1[b * Nn + i0 + tid];
    if (tid < 128) st2[tid] = g_t2[b * Nn + tid];
    __syncthreads();

    int warp = tid >> 5, lane = tid & 31;
    for (int i = warp; i < 64; i += 8) {
        int row = i0 + i;
        float4 ef = ((const float4*)(edge + ((size_t)b * Nn + row) * Nn))[lane];
        int4  av  = ((const int4*)(adj  + ((size_t)b * Nn + row) * Nn))[lane];
        float si = st1[i];
        int j0 = lane * 4;
        float v0 = si + st2[j0 + 0] + ef.x * ae; v0 = v0 >= 0.f ? v0 : 0.2f * v0; v0 = av.x > 0 ? v0 : -9e15f;
        float v1 = si + st2[j0 + 1] + ef.y * ae; v1 = v1 >= 0.f ? v1 : 0.2f * v1; v1 = av.y > 0 ? v1 : -9e15f;
        float v2 = si + st2[j0 + 2] + ef.z * ae; v2 = v2 >= 0.f ? v2 : 0.2f * v2; v2 = av.z > 0 ? v2 : -9e15f;
        float v3 = si + st2[j0 + 3] + ef.w * ae; v3 = v3 >= 0.f ? v3 : 0.2f * v3; v3 = av.w > 0 ? v3 : -9e15f;
        float m = fmaxf(fmaxf(v0, v1), fmaxf(v2, v3));
#pragma unroll
        for (int o = 16; o; o >>= 1) m = fmaxf(m, __shfl_xor_sync(0xffffffffu, m, o));
        float e0 = __expf(v0 - m), e1 = __expf(v1 - m), e2 = __expf(v2 - m), e3 = __expf(v3 - m);
        float s = e0 + e1 + e2 + e3;
#pragma unroll
        for (int o = 16; o; o >>= 1) s += __shfl_xor_sync(0xffffffffu, s, o);
        float inv = 1.f / s;
        uint4 o4;
        o4.x = to_tf32(e0 * inv); o4.y = to_tf32(e1 * inv);
        o4.z = to_tf32(e2 * inv); o4.w = to_tf32(e3 * inv);
        *(uint4*)&sAtt[i * AT_STR + lane * 4] = o4;
    }
    __syncthreads();

    int wr = warp >> 2, wc = warp & 3;
    int lr4 = lane >> 2, lc4 = lane & 3;

    for (int ch = 0; ch < 8; ch++) {
        const float* wp = g_Wx + (size_t)b * Nn * HID + ch * 64;
        for (int i = tid; i < 128 * 16; i += 256) {
            int r = i >> 4, c = (i & 15) * 4;
            float4 v = *(const float4*)(wp + (size_t)r * HID + c);
            uint4 t;
            t.x = to_tf32(v.x); t.y = to_tf32(v.y);
            t.z = to_tf32(v.z); t.w = to_tf32(v.w);
            *(uint4*)&sWx[r * WH_STR + c] = t;
        }
        __syncthreads();

        float acc[2][2][4];
#pragma unroll
        for (int mt = 0; mt < 2; mt++)
#pragma unroll
            for (int nt = 0; nt < 2; nt++)
#pragma unroll
                for (int i = 0; i < 4; i++) acc[mt][nt][i] = 0.f;

#pragma unroll
        for (int kk = 0; kk < 128; kk += 8) {
            u32 afr[2][4], bfr[2][2];
#pragma unroll
            for (int mt = 0; mt < 2; mt++) {
                int r0 = wr * 32 + mt * 16 + lr4;
                int c0 = kk + lc4;
                afr[mt][0] = sAtt[r0 * AT_STR + c0];
                afr[mt][1] = sAtt[(r0 + 8) * AT_STR + c0];
                afr[mt][2] = sAtt[r0 * AT_STR + c0 + 4];
                afr[mt][3] = sAtt[(r0 + 8) * AT_STR + c0 + 4];
            }
#pragma unroll
            for (int nt = 0; nt < 2; nt++) {
                int col = wc * 16 + nt * 8 + lr4;
                bfr[nt][0] = sWx[(kk + lc4) * WH_STR + col];
                bfr[nt][1] = sWx[(kk + lc4 + 4) * WH_STR + col];
            }
#pragma unroll
            for (int mt = 0; mt < 2; mt++)
#pragma unroll
                for (int nt = 0; nt < 2; nt++)
                    mma_tf32(acc[mt][nt], afr[mt], bfr[nt]);
        }

        float cs[2][2];
#pragma unroll
        for (int nt = 0; nt < 2; nt++) {
            cs[nt][0] = 0.f; cs[nt][1] = 0.f;
#pragma unroll
            for (int mt = 0; mt < 2; mt++) {
                cs[nt][0] += elu1(acc[mt][nt][0]) + elu1(acc[mt][nt][2]);
                cs[nt][1] += elu1(acc[mt][nt][1]) + elu1(acc[mt][nt][3]);
            }
        }
#pragma unroll
        for (int o = 4; o <= 16; o <<= 1) {
#pragma unroll
            for (int nt = 0; nt < 2; nt++) {
                cs[nt][0] += __shfl_xor_sync(0xffffffffu, cs[nt][0], o);
                cs[nt][1] += __shfl_xor_sync(0xffffffffu, cs[nt][1], o);
            }
        }
        if (lr4 == 0) {
#pragma unroll
            for (int nt = 0; nt < 2; nt++) {
                int col = wc * 16 + nt * 8 + lc4 * 2;
                scratch[wr * 64 + col]     = cs[nt][0];
                scratch[wr * 64 + col + 1] = cs[nt][1];
            }
        }
        __syncthreads();
        if (tid < 64)
            g_gatp[((size_t)b * 2 + hb) * HID + ch * 64 + tid] =
                scratch[tid] + scratch[64 + tid];
        __syncthreads();
    }
}

// ---------------------------------------------------------------------------
__global__ void gat_reduce_kernel()
{
    int idx = blockIdx.x * blockDim.x + threadIdx.x;
    if (idx >= Bq * HID) return;
    int b = idx >> 9, c = idx & 511;
    g_gat[idx] = (g_gatp[((size_t)b * 2) * HID + c] +
                  g_gatp[((size_t)b * 2 + 1) * HID + c]) * (1.f / 128.f);
}

// ---------------------------------------------------------------------------
__global__ void final_kernel(const float* __restrict__ X,
                             const float* __restrict__ W,
                             const float* __restrict__ bias,
                             float* __restrict__ out)
{
    int idx = blockIdx.x * blockDim.x + threadIdx.x;
    if (idx >= Bq * TASKS) return;
    int b = idx / TASKS, t = idx - b * TASKS;
    const float* x = X + (size_t)b * HID;
    float s = bias[t];
    for (int d = 0; d < HID; d++) s += x[d] * W[d * TASKS + t];
    out[idx] = s;
}

// ---------------------------------------------------------------------------
extern "C" void kernel_launch(void* const* d_in, const int* in_sizes, int n_in,
                              void* d_out, int out_size)
{
    const float* h        = (const float*)d_in[0];
    const int*   adj      = (const int*)d_in[1];
    const float* edge     = (const float*)d_in[2];
    const float* fp       = (const float*)d_in[3];
    const float* W_heads  = (const float*)d_in[4];
    const float* a1_heads = (const float*)d_in[5];
    const float* a2_heads = (const float*)d_in[6];
    const float* ae_heads = (const float*)d_in[7];
    const float* W_out    = (const float*)d_in[8];
    const float* a1_out   = (const float*)d_in[9];
    const float* a2_out   = (const float*)d_in[10];
    const float* ae_out   = (const float*)d_in[11];
    const float* fc1_w    = (const float*)d_in[12];
    const float* fc1_b    = (const float*)d_in[13];
    const float* fc2_w    = (const float*)d_in[14];
    const float* fc2_b    = (const float*)d_in[15];
    const float* q_w      = (const float*)d_in[16];
    const float* q_b      = (const float*)d_in[17];
    // k_w (18), k_b (19) unused: softmax over size-1 axis == 1 -> fused = q+v
    const float* v_w      = (const float*)d_in[20];
    const float* v_b      = (const float*)d_in[21];
    const float* o_w      = (const float*)d_in[22];
    const float* o_b      = (const float*)d_in[23];
    const float* ffn1_w   = (const float*)d_in[24];
    const float* ffn1_b   = (const float*)d_in[25];
    const float* ffn2_w   = (const float*)d_in[26];
    const float* ffn2_b   = (const float*)d_in[27];
    float* out = (float*)d_out;

    float *Wh, *x, *gat, *fpnh, *fpn, *buf1, *buf2, *Wx, *Wcat;
    cudaGetSymbolAddress((void**)&Wh, g_Wh);
    cudaGetSymbolAddress((void**)&x, g_x);
    cudaGetSymbolAddress((void**)&Wx, g_Wx);
    cudaGetSymbolAddress((void**)&gat, g_gat);
    cudaGetSymbolAddress((void**)&fpnh, g_fpnh);
    cudaGetSymbolAddress((void**)&fpn, g_fpn);
    cudaGetSymbolAddress((void**)&buf1, g_buf1);
    cudaGetSymbolAddress((void**)&buf2, g_buf2);
    cudaGetSymbolAddress((void**)&Wcat, g_Wcat);

    const int ATT1_SMEM = (128 * WH_STR + 64 * AT_STR + 192) * 4;
    const int ATT2_SMEM = (64 * AT_STR + 128 * WH_STR + 320) * 4;
    cudaFuncSetAttribute(attn1_kernel, cudaFuncAttributeMaxDynamicSharedMemorySize, ATT1_SMEM);
    cudaFuncSetAttribute(attn2_kernel, cudaFuncAttributeMaxDynamicSharedMemorySize, ATT2_SMEM);

    const int M1 = Bq * Nn;  // 65536

    // 1. Wcat transpose
    wcat_kernel<<<(NHEADS * F_IN * NHID + 255) / 256, 256>>>(W_heads);

    // 2. Wh = h @ Wcat  (fast tf32)
    {
        dim3 grid(HID / 128, M1 / 128);
        sgemm_tc_kernel<<<grid, 256>>>(h, Wcat, nullptr, Wh, M1, HID, F_IN, 0);
    }

    // 3. s1/s2
    s12_kernel<<<(Bq * NHEADS * Nn * 32) / 256, 256>>>(a1_heads, a2_heads);

    // 4. attn1 (tf32 mma)
    attn1_kernel<<<Bq * NHEADS * 2, 256, ATT1_SMEM>>>(ae_heads, adj, edge);

    // 5. Wx = x @ W_out (fast tf32)
    {
        dim3 grid(HID / 128, M1 / 128);
        sgemm_tc_kernel<<<grid, 256>>>(x, W_out, nullptr, Wx, M1, HID, HID, 0);
    }

    // 6. t1/t2
    t12_kernel<<<(Bq * Nn * 32) / 256, 256>>>(a1_out, a2_out);

    // 7. attn2 (tf32 mma) + mean reduce
    attn2_kernel<<<Bq * 2, 256, ATT2_SMEM>>>(ae_out, adj, edge);
    gat_reduce_kernel<<<(Bq * HID + 255) / 256, 256>>>();

    // 8. FPN (exact fp32 tail GEMMs, 64x64 tiles -> 64 CTAs)
    {
        dim3 grid(HID / 64, Bq / 64);
        tail_gemm_kernel<<<grid, 256>>>(fp, fc1_w, fc1_b, fpnh, Bq, HID, FP_DIM, 1 | 2);
        tail_gemm_kernel<<<grid, 256>>>(fpnh, fc2_w, fc2_b, fpn, Bq, HID, HID, 1);
    }

    // 9. fusion + FFN (exact fp32 tail GEMMs)
    {
        dim3 grid(HID / 64, Bq / 64);
        tail_gemm_kernel<<<grid, 256>>>(gat, q_w, q_b, buf1, Bq, HID, HID, 1);
        tail_gemm_kernel<<<grid, 256>>>(fpn, v_w, v_b, buf1, Bq, HID, HID, 1 | 4);
        tail_gemm_kernel<<<grid, 256>>>(buf1, o_w, o_b, buf2, Bq, HID, HID, 1 | 2);
        tail_gemm_kernel<<<grid, 256>>>(buf2, ffn1_w, ffn1_b, buf1, Bq, HID, HID, 1 | 2);
    }

    // 10. final projection
    final_kernel<<<(Bq * TASKS + 255) / 256, 256>>>(buf1, ffn2_w, ffn2_b, out);
}